// round 7
// baseline (speedup 1.0000x reference)
#include <cuda_runtime.h>
#include <cuda_bf16.h>
#include <cuda_fp16.h>
#include <math.h>

// Problem dims
#define B_    64
#define HDIM  1024
#define SLEN  256
#define GDIM  4096      // 4*H
#define EDIM  512
#define IN0   1536

#define WSM_U4 12288    // resident weights per CTA: 192KB = 12288 uint4
#define STG_U4 1024     // one A-stage buffer: 16KB = 1024 uint4 (2 bufs)

// ---------------- device scratch (no allocs allowed) ----------------
__device__ float g_xw[67108864];        // [S][B][4H] (268MB): xw + pre0 folded in
__device__ float g_pre0[B_ * GDIM];     // static-part gate precompute (incl. biases l0)
__device__ float g_bias1[GDIM];         // b_ih1 + b_hh1
__device__ uint4 g_wpr[1572864];        // fp16 packed weights [mat(3)][ctile(128)][k16(64)][nb(2)][lane(32)] (24MB)
__device__ uint4 g_h0p[16384];          // fp16 packed h0 ping-pong: [slot(2)][wm(2)][k16(64)][mt(2)][lane(32)]
__device__ uint4 g_h1p[16384];          // fp16 packed h1 ping-pong
__device__ float g_c0[B_ * HDIM];
__device__ float g_c1[B_ * HDIM];

// grid barrier state
__device__ volatile unsigned g_bar_cnt;
__device__ volatile unsigned g_bar_gen;

// ---------------- helpers ----------------
__device__ __forceinline__ unsigned f2tf(float x) {
    unsigned u;
    asm("cvt.rna.tf32.f32 %0, %1;" : "=r"(u) : "f"(x));
    return u;
}

__device__ __forceinline__ unsigned pkh(float a, float b) {
    __half2 h = __halves2half2(__float2half_rn(a), __float2half_rn(b));
    return *(unsigned*)&h;
}

// tf32 m16n8k8 (precompute xw GEMM only)
__device__ __forceinline__ void mma8(float d[4], const unsigned a[4], const unsigned b[2]) {
    asm volatile(
        "mma.sync.aligned.m16n8k8.row.col.f32.tf32.tf32.f32 "
        "{%0,%1,%2,%3}, {%4,%5,%6,%7}, {%8,%9}, {%0,%1,%2,%3};\n"
        : "+f"(d[0]), "+f"(d[1]), "+f"(d[2]), "+f"(d[3])
        : "r"(a[0]), "r"(a[1]), "r"(a[2]), "r"(a[3]), "r"(b[0]), "r"(b[1]));
}

// fp16 m16n8k16, f32 accumulate (recurrent path)
__device__ __forceinline__ void mma16(float d[4], const unsigned a[4], const unsigned b[2]) {
    asm volatile(
        "mma.sync.aligned.m16n8k16.row.col.f32.f16.f16.f32 "
        "{%0,%1,%2,%3}, {%4,%5,%6,%7}, {%8,%9}, {%0,%1,%2,%3};\n"
        : "+f"(d[0]), "+f"(d[1]), "+f"(d[2]), "+f"(d[3])
        : "r"(a[0]), "r"(a[1]), "r"(a[2]), "r"(a[3]), "r"(b[0]), "r"(b[1]));
}

__device__ __forceinline__ float sigm(float x) { return 1.0f / (1.0f + __expf(-x)); }

__device__ __forceinline__ void cp_async16(uint4* dst_smem, const uint4* src) {
    unsigned saddr;
    asm("{ .reg .u64 t; cvta.to.shared.u64 t, %1; cvt.u32.u64 %0, t; }"
        : "=r"(saddr) : "l"(dst_smem));
    asm volatile("cp.async.cg.shared.global [%0], [%1], 16;\n" :: "r"(saddr), "l"(src));
}

// packed-h half index within one slot (65536 halves per slot)
__device__ __forceinline__ int hp_idx(int b, int hh) {
    int wm = b >> 5;
    int mt = (b >> 4) & 1;
    int r8 = (b >> 3) & 1;
    int lane = ((b & 7) << 2) | ((hh >> 1) & 3);
    int k16 = hh >> 4;
    int reg = (((hh >> 3) & 1) << 1) | r8;
    return ((((wm << 6) | k16) * 2 + mt) * 32 + lane) * 8 + reg * 2 + (hh & 1);
}

// ---------------- init: encoder state -> packed h buffers + c ----------------
__global__ void init_pack_kernel(const float* __restrict__ eh, const float* __restrict__ ec) {
    int i = blockIdx.x * blockDim.x + threadIdx.x;
    if (i < B_ * HDIM) {
        int b = i >> 10, hh = i & 1023;
        ((__half*)g_h0p)[65536 + hp_idx(b, hh)] = __float2half_rn(eh[i]);
        ((__half*)g_h1p)[65536 + hp_idx(b, hh)] = __float2half_rn(eh[B_ * HDIM + i]);
        g_c0[i] = ec[i];
        g_c1[i] = ec[B_ * HDIM + i];
    }
}

// ---------------- bias1 fold ----------------
__global__ void bias1_kernel(const float* __restrict__ b_ih1, const float* __restrict__ b_hh1) {
    int i = blockIdx.x * blockDim.x + threadIdx.x;
    if (i < GDIM) g_bias1[i] = b_ih1[i] + b_hh1[i];
}

// ---------------- fp16 weight pre-pack: [mat][ctile(128)][k16][nb(2)][lane] ----------------
// n-tile c owns gates j = q*1024 + c*8 + u (q = n8-tile index, u = lane>>2)
__global__ void pack_w_kernel(const float* __restrict__ W0, const float* __restrict__ W1,
                              const float* __restrict__ W2) {
    int g = blockIdx.x * 256 + threadIdx.x;   // 1,572,864 total
    int lane = g & 31;
    int nb   = (g >> 5) & 1;
    int kk   = (g >> 6) & 63;
    int c    = (g >> 12) & 127;
    int m    = g >> 19;
    const float* W = (m == 0) ? W0 : ((m == 1) ? W1 : W2);
    int nl = lane >> 2;
    int j0 = (nb * 2) * 1024 + c * 8 + nl;
    int j1 = (nb * 2 + 1) * 1024 + c * 8 + nl;
    int k0 = kk * 16 + 2 * (lane & 3);
    const float* r0 = W + (size_t)j0 * HDIM + k0;
    const float* r1 = W + (size_t)j1 * HDIM + k0;
    uint4 v;
    v.x = pkh(r0[0], r0[1]);  v.y = pkh(r0[8], r0[9]);
    v.z = pkh(r1[0], r1[1]);  v.w = pkh(r1[8], r1[9]);
    g_wpr[g] = v;
}

// ---------------- pre0: biases + static part of layer-0 gates ----------------
__global__ void __launch_bounds__(256) pre0_kernel(
    const float* __restrict__ enc_outs, const int* __restrict__ langs,
    const float* __restrict__ embed, const float* __restrict__ W_ih0,
    const float* __restrict__ b_ih0, const float* __restrict__ b_hh0)
{
    __shared__ float red[256];
    const int j = blockIdx.x;
    const int t = threadIdx.x;
    const int b = t >> 2, kq = t & 3;
    const float* Wrow = W_ih0 + (size_t)j * IN0 + 512;
    const int lang = langs[b];
    const int k0 = kq * 256;
    float acc = 0.0f;
    if (kq < 2) {
        const float* src = enc_outs + (b * 128 + 127) * 512 + k0;
        #pragma unroll 8
        for (int kk = 0; kk < 256; kk++) acc += src[kk] * Wrow[k0 + kk];
    } else {
        const float* src = embed + (size_t)lang * EDIM + (k0 - 512);
        #pragma unroll 8
        for (int kk = 0; kk < 256; kk++) acc += src[kk] * Wrow[k0 + kk];
    }
    red[t] = acc;
    __syncthreads();
    if (kq == 0) {
        float s = red[t] + red[t + 1] + red[t + 2] + red[t + 3];
        g_pre0[b * GDIM + j] = s + b_ih0[j] + b_hh0[j];
    }
}

// ---------------- xw: big precompute GEMM (+ pre0 folded at store) ----------------
__global__ void __launch_bounds__(256) xw_kernel(
    const int* __restrict__ prev, const float* __restrict__ embed,
    const float* __restrict__ W_ih0)
{
    __shared__ unsigned As[128][36];
    __shared__ unsigned Bs[64][36];
    __shared__ int toks[128];
    const int tid = threadIdx.x, lane = tid & 31, warp = tid >> 5;
    const int wm = warp >> 1, wn = warp & 1;
    const int bx = blockIdx.x;
    const int by = blockIdx.y;

    if (tid < 128) {
        int r = by * 128 + tid;
        toks[tid] = prev[(r & 63) * SLEN + (r >> 6)];
    }
    __syncthreads();

    float acc[2][4][4];
    #pragma unroll
    for (int i = 0; i < 2; i++)
        #pragma unroll
        for (int jj = 0; jj < 4; jj++)
            #pragma unroll
            for (int k = 0; k < 4; k++) acc[i][jj][k] = 0.0f;

    for (int k0 = 0; k0 < EDIM; k0 += 32) {
        #pragma unroll
        for (int r = 0; r < 4; r++) {
            int idx = tid + r * 256;
            int row = idx >> 3, c4 = idx & 7;
            float4 v = *(const float4*)(embed + (size_t)toks[row] * EDIM + k0 + c4 * 4);
            As[row][c4 * 4 + 0] = f2tf(v.x); As[row][c4 * 4 + 1] = f2tf(v.y);
            As[row][c4 * 4 + 2] = f2tf(v.z); As[row][c4 * 4 + 3] = f2tf(v.w);
        }
        #pragma unroll
        for (int r = 0; r < 2; r++) {
            int idx = tid + r * 256;
            int n = idx >> 3, c4 = idx & 7;
            int j = bx * 64 + n;
            float4 v = *(const float4*)(W_ih0 + (size_t)j * IN0 + k0 + c4 * 4);
            Bs[n][c4 * 4 + 0] = f2tf(v.x); Bs[n][c4 * 4 + 1] = f2tf(v.y);
            Bs[n][c4 * 4 + 2] = f2tf(v.z); Bs[n][c4 * 4 + 3] = f2tf(v.w);
        }
        __syncthreads();
        #pragma unroll
        for (int kc = 0; kc < 4; kc++) {
            const int kb = kc * 8 + (lane & 3);
            unsigned a[2][4], b[4][2];
            #pragma unroll
            for (int mt = 0; mt < 2; mt++) {
                int r0 = wm * 32 + mt * 16 + (lane >> 2);
                a[mt][0] = As[r0][kb];     a[mt][1] = As[r0 + 8][kb];
                a[mt][2] = As[r0][kb + 4]; a[mt][3] = As[r0 + 8][kb + 4];
            }
            #pragma unroll
            for (int nt = 0; nt < 4; nt++) {
                int n0 = wn * 32 + nt * 8 + (lane >> 2);
                b[nt][0] = Bs[n0][kb]; b[nt][1] = Bs[n0][kb + 4];
            }
            #pragma unroll
            for (int mt = 0; mt < 2; mt++)
                #pragma unroll
                for (int nt = 0; nt < 4; nt++)
                    mma8(acc[mt][nt], a[mt], b[nt]);
        }
        __syncthreads();
    }
    #pragma unroll
    for (int mt = 0; mt < 2; mt++)
        #pragma unroll
        for (int nt = 0; nt < 4; nt++) {
            int row = wm * 32 + mt * 16 + (lane >> 2);
            int col = bx * 64 + wn * 32 + nt * 8 + 2 * (lane & 3);
            int rg0 = by * 128 + row;
            int rg1 = rg0 + 8;
            size_t base0 = (size_t)rg0 * GDIM + col;
            size_t base1 = (size_t)rg1 * GDIM + col;
            const float* p0 = g_pre0 + (rg0 & 63) * GDIM + col;
            const float* p1 = g_pre0 + (rg1 & 63) * GDIM + col;
            *(float2*)(g_xw + base0) = make_float2(acc[mt][nt][0] + p0[0], acc[mt][nt][1] + p0[1]);
            *(float2*)(g_xw + base1) = make_float2(acc[mt][nt][2] + p1[0], acc[mt][nt][3] + p1[1]);
        }
}

// ---------------- grid-wide barrier (all 128 CTAs co-resident) ----------------
__device__ __forceinline__ void grid_sync() {
    __syncthreads();
    if (threadIdx.x == 0) {
        unsigned gen = g_bar_gen;
        __threadfence();
        if (atomicAdd((unsigned*)&g_bar_cnt, 1u) == 127u) {
            g_bar_cnt = 0;
            __threadfence();
            g_bar_gen = gen + 1;
        } else {
            while (g_bar_gen == gen) { __nanosleep(16); }
        }
        __threadfence();
    }
    __syncthreads();
}

// ---------------- A-chunk producer: one step = 2 k16 chunks per wk group = 16KB ----------
// Stage layout (uint4): id = w(4)*256 + j(2)*128 + wm(2)*64 + mt(2)*32 + lane(32)
// chunk id s = w*48 + step*2 + j; mat m = s>>6 (0,1: h0; 2: h1); kk = s&63
__device__ __forceinline__ void produce_step(uint4* dst, int step, int pa, int pb) {
    const int tid = threadIdx.x;
    #pragma unroll
    for (int o = 0; o < 4; o++) {
        int id = o * 256 + tid;
        int lane = id & 31;
        int mt  = (id >> 5) & 1;
        int wm_ = (id >> 6) & 1;
        int j   = (id >> 7) & 1;
        int w   = (id >> 8) & 3;
        int s = w * 48 + step * 2 + j;
        int m = s >> 6;
        int kk = s & 63;
        const uint4* base = (m < 2) ? (g_h0p + pa * 8192) : (g_h1p + pb * 8192);
        const uint4* src = base + wm_ * 4096 + kk * 64 + mt * 32 + lane;
        cp_async16(dst + id, src);
    }
}

#define MMA_BLOCK(ACC) do { \
    mma16(ACC[0][0], A0, B0); mma16(ACC[0][1], A0, B1); \
    mma16(ACC[0][2], A0, B2); mma16(ACC[0][3], A0, B3); \
    mma16(ACC[1][0], A1, B0); mma16(ACC[1][1], A1, B1); \
    mma16(ACC[1][2], A1, B2); mma16(ACC[1][3], A1, B3); } while (0)

#define RED_STORE(BASE, ACC) do { \
    _Pragma("unroll") for (int mt = 0; mt < 2; mt++) \
    _Pragma("unroll") for (int nt = 0; nt < 4; nt++) { \
        int row = wm * 32 + mt * 16 + (lane >> 2); \
        int col = nt * 8 + 2 * (lane & 3); \
        (BASE)[row * 36 + col]           = ACC[mt][nt][0]; \
        (BASE)[row * 36 + col + 1]       = ACC[mt][nt][1]; \
        (BASE)[(row + 8) * 36 + col]     = ACC[mt][nt][2]; \
        (BASE)[(row + 8) * 36 + col + 1] = ACC[mt][nt][3]; } } while (0)

#define RED_ADD(BASE, ACC) do { \
    _Pragma("unroll") for (int mt = 0; mt < 2; mt++) \
    _Pragma("unroll") for (int nt = 0; nt < 4; nt++) { \
        int row = wm * 32 + mt * 16 + (lane >> 2); \
        int col = nt * 8 + 2 * (lane & 3); \
        (BASE)[row * 36 + col]           += ACC[mt][nt][0]; \
        (BASE)[row * 36 + col + 1]       += ACC[mt][nt][1]; \
        (BASE)[(row + 8) * 36 + col]     += ACC[mt][nt][2]; \
        (BASE)[(row + 8) * 36 + col + 1] += ACC[mt][nt][3]; } } while (0)

// ---------------- persistent LSTM kernel: merged layers, W resident in SMEM ----------------
// 128 CTAs, each owns 8 hidden units (n-tile of 32 gates) for BOTH layers.
// 8 warps: wm = warp&1 (M half), wk = warp>>1 (split-K quarter over flat K=3072).
__global__ void __launch_bounds__(256, 1) persist_kernel(float* __restrict__ out) {
    extern __shared__ uint4 dynsmem[];
    uint4* Wsm = dynsmem;                    // [0, 12288): resident weights (192KB)
    uint4* stg = dynsmem + WSM_U4;           // 2 x 1024 uint4 A stages (32KB)
    float* gsr = (float*)stg;                // reduce buffers alias stages (2x64x36 floats)

    const int tid = threadIdx.x, lane = tid & 31, warp = tid >> 5;
    const int wm = warp & 1, wk = warp >> 1;
    const int c = blockIdx.x;

    // ---- load resident weight slice (192KB) ----
    #pragma unroll 8
    for (int p = 0; p < 48; p++) {
        int r_idx = tid + p * 256;
        int m = r_idx >> 12;
        int rem = r_idx & 4095;
        cp_async16(Wsm + r_idx, g_wpr + (size_t)m * 524288 + c * 4096 + rem);
    }
    asm volatile("cp.async.commit_group;\n");
    asm volatile("cp.async.wait_group 0;\n");
    __syncthreads();

    for (int i = 0; i <= 256; i++) {
        const int pa = (i + 1) & 1;     // h slot to read (written last iter)
        const int pb = i & 1;           // h0 slot to write

        float acc0[2][4][4], acc1[2][4][4];
        #pragma unroll
        for (int a = 0; a < 2; a++)
            #pragma unroll
            for (int b = 0; b < 4; b++)
                #pragma unroll
                for (int k = 0; k < 4; k++) { acc0[a][b][k] = 0.0f; acc1[a][b][k] = 0.0f; }

        produce_step(stg, 0, pa, pb);
        asm volatile("cp.async.commit_group;\n");

        for (int r = 0; r < 24; r++) {
            asm volatile("cp.async.wait_group 0;\n");
            __syncthreads();
            if (r < 23) {
                produce_step(stg + ((r + 1) & 1) * STG_U4, r + 1, pa, pb);
                asm volatile("cp.async.commit_group;\n");
            }
            const uint4* sb = stg + (r & 1) * STG_U4;
            #pragma unroll
            for (int j = 0; j < 2; j++) {
                int s = wk * 48 + 2 * r + j;
                const uint4* Ac = sb + wk * 256 + j * 128 + wm * 64;
                uint4 a0 = Ac[lane], a1 = Ac[32 + lane];
                const uint4* Wc = Wsm + s * 64;
                uint4 w0 = Wc[lane], w1 = Wc[32 + lane];
                unsigned A0[4] = {a0.x, a0.y, a0.z, a0.w};
                unsigned A1[4] = {a1.x, a1.y, a1.z, a1.w};
                unsigned B0[2] = {w0.x, w0.y}, B1[2] = {w0.z, w0.w};
                unsigned B2[2] = {w1.x, w1.y}, B3[2] = {w1.z, w1.w};
                if (s < 64) { MMA_BLOCK(acc0); } else { MMA_BLOCK(acc1); }
            }
        }
        __syncthreads();   // mainloop done; stage mem becomes reduce buffers

        // split-K reduce: set0 = gates0 (mat0), set1 = gates1 (mat1+mat2)
        // wk0: set0 only. wk1: both. wk2/wk3: set1 only.
        if (wk == 0) RED_STORE(gsr, acc0);
        if (wk == 3) RED_STORE(gsr + 2304, acc1);
        __syncthreads();
        if (wk == 1) { RED_ADD(gsr, acc0); RED_ADD(gsr + 2304, acc1); }
        __syncthreads();
        if (wk == 2) RED_ADD(gsr + 2304, acc1);
        __syncthreads();

        // epilogue: 1024 cell updates (2 layers x 64 b x 8 u), 4 per thread
        const float* xw_t = g_xw + (size_t)i * (B_ * GDIM);
        #pragma unroll
        for (int ee = 0; ee < 4; ee++) {
            int e = tid + ee * 256;
            int set = e >> 9, b = (e >> 3) & 63, u = e & 7;
            int hh = c * 8 + u;
            if (set == 0) {
                if (i < 256) {
                    float g0 = gsr[b * 36 + u]      + xw_t[b * GDIM + hh];
                    float g1 = gsr[b * 36 + 8 + u]  + xw_t[b * GDIM + 1024 + hh];
                    float g2 = gsr[b * 36 + 16 + u] + xw_t[b * GDIM + 2048 + hh];
                    float g3 = gsr[b * 36 + 24 + u] + xw_t[b * GDIM + 3072 + hh];
                    float ci = g_c0[b * HDIM + hh];
                    float cn = sigm(g1) * ci + sigm(g0) * tanhf(g2);
                    g_c0[b * HDIM + hh] = cn;
                    float hn = sigm(g3) * tanhf(cn);
                    ((__half*)g_h0p)[pb * 65536 + hp_idx(b, hh)] = __float2half_rn(hn);
                }
            } else {
                if (i >= 1) {
                    int t1 = i - 1;
                    float g0 = gsr[2304 + b * 36 + u]      + g_bias1[hh];
                    float g1 = gsr[2304 + b * 36 + 8 + u]  + g_bias1[1024 + hh];
                    float g2 = gsr[2304 + b * 36 + 16 + u] + g_bias1[2048 + hh];
                    float g3 = gsr[2304 + b * 36 + 24 + u] + g_bias1[3072 + hh];
                    float ci = g_c1[b * HDIM + hh];
                    float cn = sigm(g1) * ci + sigm(g0) * tanhf(g2);
                    g_c1[b * HDIM + hh] = cn;
                    float hn = sigm(g3) * tanhf(cn);
                    ((__half*)g_h1p)[pa * 65536 + hp_idx(b, hh)] = __float2half_rn(hn);
                    out[(size_t)t1 * (B_ * HDIM) + b * HDIM + hh] = hn;
                }
            }
        }
        grid_sync();
    }
}

// ---------------- launch ----------------
extern "C" void kernel_launch(void* const* d_in, const int* in_sizes, int n_in,
                              void* d_out, int out_size) {
    const int*   prev   = (const int*)d_in[0];
    const int*   langs  = (const int*)d_in[1];
    const float* enc_o  = (const float*)d_in[2];
    const float* enc_h  = (const float*)d_in[3];
    const float* enc_c  = (const float*)d_in[4];
    const float* embed  = (const float*)d_in[5];
    const float* W_ih0  = (const float*)d_in[6];
    const float* W_hh0  = (const float*)d_in[7];
    const float* b_ih0  = (const float*)d_in[8];
    const float* b_hh0  = (const float*)d_in[9];
    const float* W_ih1  = (const float*)d_in[10];
    const float* W_hh1  = (const float*)d_in[11];
    const float* b_ih1  = (const float*)d_in[12];
    const float* b_hh1  = (const float*)d_in[13];
    float* out = (float*)d_out;

    const int smem_bytes = (WSM_U4 + 2 * STG_U4) * 16;   // 229376 B
    static int attr_done = 0;
    if (!attr_done) {
        cudaFuncSetAttribute(persist_kernel, cudaFuncAttributeMaxDynamicSharedMemorySize,
                             smem_bytes);
        attr_done = 1;
    }

    init_pack_kernel<<<256, 256>>>(enc_h, enc_c);
    bias1_kernel<<<16, 256>>>(b_ih1, b_hh1);
    pack_w_kernel<<<6144, 256>>>(W_hh0, W_ih1, W_hh1);
    pre0_kernel<<<GDIM, 256>>>(enc_o, langs, embed, W_ih0, b_ih0, b_hh0);
    xw_kernel<<<dim3(GDIM / 64, (SLEN * B_) / 128), 256>>>(prev, embed, W_ih0);

    persist_kernel<<<128, 256, smem_bytes>>>(out);
}